// round 6
// baseline (speedup 1.0000x reference)
#include <cuda_runtime.h>
#include <cstdint>
#include <mma.h>
#include <math.h>

using namespace nvcuda;

#define DM   1024
#define NB   4
#define SQ   4096

// Scratch (device globals: the sanctioned alloc-free workaround)
__device__ float g_q[(size_t)NB * SQ * DM];
__device__ float g_k[(size_t)NB * SQ * DM];
__device__ float g_v[(size_t)NB * SQ * DM];
__device__ float g_s[(size_t)NB * SQ * SQ];

__device__ __forceinline__ float4 tf32_rn4(float4 v)
{
    float4 r;
    r.x = wmma::__float_to_tf32(v.x);
    r.y = wmma::__float_to_tf32(v.y);
    r.z = wmma::__float_to_tf32(v.z);
    r.w = wmma::__float_to_tf32(v.w);
    return r;
}

// ===========================================================================
// Plain TF32:  C = alpha * A(M,K) * B(N,K)^T   (both row-major, K contiguous)
// 128x128x32 tile, 256 threads (8 warps, 4x2), warp tile 32x64.
// Register-staged double buffering. RN tf32 conversion at smem-store time.
// ===========================================================================
__global__ void __launch_bounds__(256) gemm_abT_plain(
    const float* __restrict__ Ab, const float* __restrict__ Bb,
    float* __restrict__ Cb, int N, int K,
    long sA, long sB, long sC, float alpha)
{
    constexpr int BM = 128, BN = 128, BK = 32, LD = BK + 4;
    extern __shared__ float sm[];
    float* As = sm;                    // [2][BM][LD]
    float* Bs = sm + 2 * BM * LD;      // [2][BN][LD]

    const float* A = Ab + (long)blockIdx.z * sA;
    const float* B = Bb + (long)blockIdx.z * sB;
    float*       C = Cb + (long)blockIdx.z * sC;

    const int tm   = blockIdx.y * BM;
    const int tn   = blockIdx.x * BN;
    const int tid  = threadIdx.x;
    const int warp = tid >> 5;
    const int wm   = (warp >> 1) * 32;   // 4 warp rows
    const int wn   = (warp & 1) * 64;    // 2 warp cols

    wmma::fragment<wmma::accumulator, 16, 16, 8, float> acc[2][4];
#pragma unroll
    for (int i = 0; i < 2; i++)
#pragma unroll
        for (int j = 0; j < 4; j++) wmma::fill_fragment(acc[i][j], 0.0f);

    const int r0 = tid >> 3;           // 0..31 base row (x4 iters -> 128)
    const int c0 = (tid & 7) << 2;     // 0..28 col

    float4 ra[4], rb[4];

    // Prologue: tile 0 -> regs -> (tf32 RN) -> smem buf 0
#pragma unroll
    for (int i = 0; i < 4; i++) {
        int r = r0 + i * 32;
        ra[i] = *(const float4*)&A[(long)(tm + r) * K + c0];
        rb[i] = *(const float4*)&B[(long)(tn + r) * K + c0];
    }
#pragma unroll
    for (int i = 0; i < 4; i++) {
        int r = r0 + i * 32;
        *(float4*)&As[r * LD + c0] = tf32_rn4(ra[i]);
        *(float4*)&Bs[r * LD + c0] = tf32_rn4(rb[i]);
    }
    __syncthreads();

    int buf = 0;
    for (int kk = 0; kk < K; kk += BK) {
        const bool has_next = (kk + BK) < K;
        if (has_next) {
#pragma unroll
            for (int i = 0; i < 4; i++) {
                int r = r0 + i * 32;
                ra[i] = *(const float4*)&A[(long)(tm + r) * K + kk + BK + c0];
                rb[i] = *(const float4*)&B[(long)(tn + r) * K + kk + BK + c0];
            }
        }

#pragma unroll
        for (int ks = 0; ks < BK; ks += 8) {
            wmma::fragment<wmma::matrix_a, 16, 16, 8, wmma::precision::tf32, wmma::row_major> af[2];
            wmma::fragment<wmma::matrix_b, 16, 16, 8, wmma::precision::tf32, wmma::col_major> bf[4];
#pragma unroll
            for (int i = 0; i < 2; i++)
                wmma::load_matrix_sync(af[i], &As[(buf * BM + wm + i * 16) * LD + ks], LD);
#pragma unroll
            for (int j = 0; j < 4; j++)
                wmma::load_matrix_sync(bf[j], &Bs[(buf * BN + wn + j * 16) * LD + ks], LD);
#pragma unroll
            for (int i = 0; i < 2; i++)
#pragma unroll
                for (int j = 0; j < 4; j++)
                    wmma::mma_sync(acc[i][j], af[i], bf[j], acc[i][j]);
        }

        if (has_next) {
            int nb = buf ^ 1;
#pragma unroll
            for (int i = 0; i < 4; i++) {
                int r = r0 + i * 32;
                *(float4*)&As[(nb * BM + r) * LD + c0] = tf32_rn4(ra[i]);
                *(float4*)&Bs[(nb * BN + r) * LD + c0] = tf32_rn4(rb[i]);
            }
        }
        __syncthreads();
        buf ^= 1;
    }

#pragma unroll
    for (int i = 0; i < 2; i++)
#pragma unroll
        for (int j = 0; j < 4; j++) {
#pragma unroll
            for (int e = 0; e < acc[i][j].num_elements; e++) acc[i][j].x[e] *= alpha;
            wmma::store_matrix_sync(&C[(long)(tm + wm + i * 16) * N + tn + wn + j * 16],
                                    acc[i][j], N, wmma::mem_row_major);
        }
}

// ===========================================================================
// Plain TF32:  C = A(M,K) * B(K,N)   (row-major). Same pipeline; B tile 32x128.
// RN tf32 conversion at smem-store time.
// ===========================================================================
__global__ void __launch_bounds__(256) gemm_ab_plain(
    const float* __restrict__ Ab, const float* __restrict__ Bb,
    float* __restrict__ Cb, int N, int K,
    long sA, long sB, long sC)
{
    constexpr int BM = 128, BN = 128, BK = 32, LDA = BK + 4, LDB = BN + 4;
    extern __shared__ float sm[];
    float* As = sm;                    // [2][BM][LDA]
    float* Bs = sm + 2 * BM * LDA;     // [2][BK][LDB]

    const float* A = Ab + (long)blockIdx.z * sA;
    const float* B = Bb + (long)blockIdx.z * sB;
    float*       C = Cb + (long)blockIdx.z * sC;

    const int tm   = blockIdx.y * BM;
    const int tn   = blockIdx.x * BN;
    const int tid  = threadIdx.x;
    const int warp = tid >> 5;
    const int wm   = (warp >> 1) * 32;
    const int wn   = (warp & 1) * 64;

    wmma::fragment<wmma::accumulator, 16, 16, 8, float> acc[2][4];
#pragma unroll
    for (int i = 0; i < 2; i++)
#pragma unroll
        for (int j = 0; j < 4; j++) wmma::fill_fragment(acc[i][j], 0.0f);

    const int ra0 = tid >> 3;          // A: 0..31 (x4 -> 128 rows), col (tid&7)*4
    const int ca0 = (tid & 7) << 2;
    const int rb0 = tid >> 5;          // B: 0..7 (x4 -> 32 rows), col (tid&31)*4
    const int cb0 = (tid & 31) << 2;

    float4 ra[4], rb[4];

    // Prologue: tile 0
#pragma unroll
    for (int i = 0; i < 4; i++) {
        ra[i] = *(const float4*)&A[(long)(tm + ra0 + i * 32) * K + ca0];
        rb[i] = *(const float4*)&B[(long)(rb0 + i * 8) * N + tn + cb0];
    }
#pragma unroll
    for (int i = 0; i < 4; i++) {
        *(float4*)&As[(ra0 + i * 32) * LDA + ca0] = tf32_rn4(ra[i]);
        *(float4*)&Bs[(rb0 + i * 8) * LDB + cb0]  = tf32_rn4(rb[i]);
    }
    __syncthreads();

    int buf = 0;
    for (int kk = 0; kk < K; kk += BK) {
        const bool has_next = (kk + BK) < K;
        if (has_next) {
#pragma unroll
            for (int i = 0; i < 4; i++) {
                ra[i] = *(const float4*)&A[(long)(tm + ra0 + i * 32) * K + kk + BK + ca0];
                rb[i] = *(const float4*)&B[(long)(kk + BK + rb0 + i * 8) * N + tn + cb0];
            }
        }

#pragma unroll
        for (int ks = 0; ks < BK; ks += 8) {
            wmma::fragment<wmma::matrix_a, 16, 16, 8, wmma::precision::tf32, wmma::row_major> af[2];
            wmma::fragment<wmma::matrix_b, 16, 16, 8, wmma::precision::tf32, wmma::row_major> bf[4];
#pragma unroll
            for (int i = 0; i < 2; i++)
                wmma::load_matrix_sync(af[i], &As[(buf * BM + wm + i * 16) * LDA + ks], LDA);
#pragma unroll
            for (int j = 0; j < 4; j++)
                wmma::load_matrix_sync(bf[j], &Bs[(buf * BK + ks) * LDB + wn + j * 16], LDB);
#pragma unroll
            for (int i = 0; i < 2; i++)
#pragma unroll
                for (int j = 0; j < 4; j++)
                    wmma::mma_sync(acc[i][j], af[i], bf[j], acc[i][j]);
        }

        if (has_next) {
            int nb = buf ^ 1;
#pragma unroll
            for (int i = 0; i < 4; i++) {
                *(float4*)&As[(nb * BM + ra0 + i * 32) * LDA + ca0] = tf32_rn4(ra[i]);
                *(float4*)&Bs[(nb * BK + rb0 + i * 8) * LDB + cb0]  = tf32_rn4(rb[i]);
            }
        }
        __syncthreads();
        buf ^= 1;
    }

#pragma unroll
    for (int i = 0; i < 2; i++)
#pragma unroll
        for (int j = 0; j < 4; j++)
            wmma::store_matrix_sync(&C[(long)(tm + wm + i * 16) * N + tn + wn + j * 16],
                                    acc[i][j], N, wmma::mem_row_major);
}

// ===========================================================================
// Precise (3xTF32):  C = A(M,K) * B(N,K)^T.  hi/lo split at smem fill;
// mainloop pure LDS + HMMA. Single smem buffer, register prefetch.
// ===========================================================================
__global__ void __launch_bounds__(256) gemm_abT_precise(
    const float* __restrict__ A, const float* __restrict__ B,
    float* __restrict__ C, int N, int K)
{
    constexpr int BM = 128, BN = 128, BK = 32, LD = BK + 4;
    extern __shared__ float sm[];
    float* Ah = sm;                    // [BM][LD]
    float* Al = Ah + BM * LD;
    float* Bh = Al + BM * LD;          // [BN][LD]
    float* Bl = Bh + BN * LD;

    const int tm   = blockIdx.y * BM;
    const int tn   = blockIdx.x * BN;
    const int tid  = threadIdx.x;
    const int warp = tid >> 5;
    const int wm   = (warp >> 1) * 32;
    const int wn   = (warp & 1) * 64;

    wmma::fragment<wmma::accumulator, 16, 16, 8, float> acc[2][4];
#pragma unroll
    for (int i = 0; i < 2; i++)
#pragma unroll
        for (int j = 0; j < 4; j++) wmma::fill_fragment(acc[i][j], 0.0f);

    const int r0 = tid >> 3;
    const int c0 = (tid & 7) << 2;

    float4 va[4], vb[4];
#pragma unroll
    for (int i = 0; i < 4; i++) {
        int r = r0 + i * 32;
        va[i] = *(const float4*)&A[(long)(tm + r) * K + c0];
        vb[i] = *(const float4*)&B[(long)(tn + r) * K + c0];
    }

    for (int kk = 0; kk < K; kk += BK) {
        // Split staged tile into hi/lo and store to smem.
#pragma unroll
        for (int i = 0; i < 4; i++) {
            int r = r0 + i * 32;
            float4 vah = tf32_rn4(va[i]);
            float4 vbh = tf32_rn4(vb[i]);
            float4 val, vbl;
            val.x = wmma::__float_to_tf32(va[i].x - vah.x);
            val.y = wmma::__float_to_tf32(va[i].y - vah.y);
            val.z = wmma::__float_to_tf32(va[i].z - vah.z);
            val.w = wmma::__float_to_tf32(va[i].w - vah.w);
            vbl.x = wmma::__float_to_tf32(vb[i].x - vbh.x);
            vbl.y = wmma::__float_to_tf32(vb[i].y - vbh.y);
            vbl.z = wmma::__float_to_tf32(vb[i].z - vbh.z);
            vbl.w = wmma::__float_to_tf32(vb[i].w - vbh.w);
            *(float4*)&Ah[r * LD + c0] = vah;
            *(float4*)&Al[r * LD + c0] = val;
            *(float4*)&Bh[r * LD + c0] = vbh;
            *(float4*)&Bl[r * LD + c0] = vbl;
        }
        __syncthreads();

        // Prefetch next tile into registers while MMAs run.
        if (kk + BK < K) {
#pragma unroll
            for (int i = 0; i < 4; i++) {
                int r = r0 + i * 32;
                va[i] = *(const float4*)&A[(long)(tm + r) * K + kk + BK + c0];
                vb[i] = *(const float4*)&B[(long)(tn + r) * K + kk + BK + c0];
            }
        }

#pragma unroll
        for (int ks = 0; ks < BK; ks += 8) {
            wmma::fragment<wmma::matrix_a, 16, 16, 8, wmma::precision::tf32, wmma::row_major> ah[2], al[2];
            wmma::fragment<wmma::matrix_b, 16, 16, 8, wmma::precision::tf32, wmma::col_major> bh[4], bl[4];
#pragma unroll
            for (int i = 0; i < 2; i++) {
                wmma::load_matrix_sync(ah[i], &Ah[(wm + i * 16) * LD + ks], LD);
                wmma::load_matrix_sync(al[i], &Al[(wm + i * 16) * LD + ks], LD);
            }
#pragma unroll
            for (int j = 0; j < 4; j++) {
                wmma::load_matrix_sync(bh[j], &Bh[(wn + j * 16) * LD + ks], LD);
                wmma::load_matrix_sync(bl[j], &Bl[(wn + j * 16) * LD + ks], LD);
            }
#pragma unroll
            for (int i = 0; i < 2; i++)
#pragma unroll
                for (int j = 0; j < 4; j++) {
                    wmma::mma_sync(acc[i][j], ah[i], bl[j], acc[i][j]);
                    wmma::mma_sync(acc[i][j], al[i], bh[j], acc[i][j]);
                    wmma::mma_sync(acc[i][j], ah[i], bh[j], acc[i][j]);
                }
        }
        __syncthreads();
    }

#pragma unroll
    for (int i = 0; i < 2; i++)
#pragma unroll
        for (int j = 0; j < 4; j++)
            wmma::store_matrix_sync(&C[(long)(tm + wm + i * 16) * N + tn + wn + j * 16],
                                    acc[i][j], N, wmma::mem_row_major);
}

// ---------------------------------------------------------------------------
// In-place row softmax over 4096-wide rows. One block (256 thr) per row.
// ---------------------------------------------------------------------------
__global__ void __launch_bounds__(256) softmax_kernel(float* __restrict__ Sg)
{
    float* row = Sg + (size_t)blockIdx.x * SQ;
    const int tid = threadIdx.x;
    __shared__ float red[8];

    float vals[16];
    float m = -3.4e38f;
#pragma unroll
    for (int i = 0; i < 16; i++) {
        vals[i] = row[tid + i * 256];
        m = fmaxf(m, vals[i]);
    }
#pragma unroll
    for (int o = 16; o; o >>= 1) m = fmaxf(m, __shfl_xor_sync(0xffffffffu, m, o));
    if ((tid & 31) == 0) red[tid >> 5] = m;
    __syncthreads();
    {
        float t = red[tid & 7];
#pragma unroll
        for (int o = 4; o; o >>= 1) t = fmaxf(t, __shfl_xor_sync(0xffffffffu, t, o));
        m = t;
    }

    float sum = 0.0f;
#pragma unroll
    for (int i = 0; i < 16; i++) {
        vals[i] = __expf(vals[i] - m);
        sum += vals[i];
    }
#pragma unroll
    for (int o = 16; o; o >>= 1) sum += __shfl_xor_sync(0xffffffffu, sum, o);
    __syncthreads();
    if ((tid & 31) == 0) red[tid >> 5] = sum;
    __syncthreads();
    {
        float t = red[tid & 7];
#pragma unroll
        for (int o = 4; o; o >>= 1) t += __shfl_xor_sync(0xffffffffu, t, o);
        sum = t;
    }

    float inv = 1.0f / sum;
#pragma unroll
    for (int i = 0; i < 16; i++) row[tid + i * 256] = vals[i] * inv;
}

// ---------------------------------------------------------------------------
extern "C" void kernel_launch(void* const* d_in, const int* in_sizes, int n_in,
                              void* d_out, int out_size)
{
    const float* x  = (const float*)d_in[0];   // (4, 4096, 1024)
    const float* Wq = (const float*)d_in[1];   // (1024, 1024)
    const float* Wk = (const float*)d_in[2];
    const float* Wv = (const float*)d_in[3];
    float* out = (float*)d_out;                // (4, 4096, 1024) fp32

    float *q, *k, *v, *s;
    cudaGetSymbolAddress((void**)&q, g_q);
    cudaGetSymbolAddress((void**)&k, g_k);
    cudaGetSymbolAddress((void**)&v, g_v);
    cudaGetSymbolAddress((void**)&s, g_s);

    constexpr int LD  = 32 + 4;
    const int smem_abT     = 2 * (128 * LD + 128 * LD) * 4;           // 73728
    const int smem_ab      = (2 * 128 * LD + 2 * 32 * (128 + 4)) * 4; // 70656
    const int smem_precise = 4 * 128 * LD * 4;                        // 73728

    cudaFuncSetAttribute(gemm_abT_plain,   cudaFuncAttributeMaxDynamicSharedMemorySize, smem_abT);
    cudaFuncSetAttribute(gemm_ab_plain,    cudaFuncAttributeMaxDynamicSharedMemorySize, smem_ab);
    cudaFuncSetAttribute(gemm_abT_precise, cudaFuncAttributeMaxDynamicSharedMemorySize, smem_precise);

    const dim3 blk(256);

    // Phase 1: QKV projections (3xTF32). M = 16384, N = K = 1024.
    {
        dim3 grid(DM / 128, (NB * SQ) / 128, 1);
        gemm_abT_precise<<<grid, blk, smem_precise>>>(x, Wq, q, DM, DM);
        gemm_abT_precise<<<grid, blk, smem_precise>>>(x, Wk, k, DM, DM);
        gemm_abT_precise<<<grid, blk, smem_precise>>>(x, Wv, v, DM, DM);
    }

    // Phase 2: scores = (Q K^T) / 32, batched.
    {
        dim3 grid(SQ / 128, SQ / 128, NB);
        gemm_abT_plain<<<grid, blk, smem_abT>>>(q, k, s, SQ, DM,
                                                (long)SQ * DM, (long)SQ * DM,
                                                (long)SQ * SQ, 1.0f / 32.0f);
    }

    // Phase 3: row softmax (in place).
    softmax_kernel<<<NB * SQ, 256>>>(s);

    // Phase 4: out = P V, batched.
    {
        dim3 grid(DM / 128, SQ / 128, NB);
        gemm_ab_plain<<<grid, blk, smem_ab>>>(s, v, out, DM, SQ,
                                              (long)SQ * SQ, (long)SQ * DM,
                                              (long)SQ * DM);
    }
}

// round 7
// speedup vs baseline: 1.2175x; 1.2175x over previous
#include <cuda_runtime.h>
#include <cstdint>
#include <mma.h>
#include <math.h>

using namespace nvcuda;

#define DM   1024
#define NB   4
#define SQ   4096

// Scratch (device globals: the sanctioned alloc-free workaround)
__device__ float g_q[(size_t)NB * SQ * DM];
__device__ float g_k[(size_t)NB * SQ * DM];
__device__ float g_v[(size_t)NB * SQ * DM];
__device__ float g_s[(size_t)NB * SQ * SQ];

__device__ __forceinline__ void cp_async16(void* dst_smem, const void* src_gmem)
{
    uint32_t d = (uint32_t)__cvta_generic_to_shared(dst_smem);
    asm volatile("cp.async.cg.shared.global [%0], [%1], 16;\n" :: "r"(d), "l"(src_gmem));
}
__device__ __forceinline__ void cp_commit() { asm volatile("cp.async.commit_group;\n" ::); }
__device__ __forceinline__ void cp_wait0()  { asm volatile("cp.async.wait_group 0;\n" ::); }
__device__ __forceinline__ void cp_wait1()  { asm volatile("cp.async.wait_group 1;\n" ::); }

// ===========================================================================
// Plain TF32:  C = alpha * A(M,K) * B(N,K)^T   (both row-major, K contiguous)
// 128x128x32 tile, 256 threads (8 warps, 4x2), warp tile 32x64.
// cp.async double buffering; RN tf32 conversion at fragment load (round-1
// numerics, bit-exact).
// ===========================================================================
__global__ void __launch_bounds__(256, 2) gemm_abT_plain(
    const float* __restrict__ Ab, const float* __restrict__ Bb,
    float* __restrict__ Cb, int N, int K,
    long sA, long sB, long sC, float alpha)
{
    constexpr int BM = 128, BN = 128, BK = 32, LD = BK + 4;
    extern __shared__ float sm[];
    float* As = sm;                    // [2][BM][LD]
    float* Bs = sm + 2 * BM * LD;      // [2][BN][LD]

    const float* A = Ab + (long)blockIdx.z * sA;
    const float* B = Bb + (long)blockIdx.z * sB;
    float*       C = Cb + (long)blockIdx.z * sC;

    const int tm   = blockIdx.y * BM;
    const int tn   = blockIdx.x * BN;
    const int tid  = threadIdx.x;
    const int warp = tid >> 5;
    const int wm   = (warp >> 1) * 32;   // 4 warp rows
    const int wn   = (warp & 1) * 64;    // 2 warp cols

    wmma::fragment<wmma::accumulator, 16, 16, 8, float> acc[2][4];
#pragma unroll
    for (int i = 0; i < 2; i++)
#pragma unroll
        for (int j = 0; j < 4; j++) wmma::fill_fragment(acc[i][j], 0.0f);

    const int r0 = tid >> 3;           // 0..31 base row (x4 iters -> 128)
    const int c0 = (tid & 7) << 2;     // 0..28 col

    auto load_tile = [&](int buf, int kk) {
#pragma unroll
        for (int i = 0; i < 4; i++) {
            int r = r0 + i * 32;
            cp_async16(&As[(buf * BM + r) * LD + c0], &A[(long)(tm + r) * K + kk + c0]);
            cp_async16(&Bs[(buf * BN + r) * LD + c0], &B[(long)(tn + r) * K + kk + c0]);
        }
        cp_commit();
    };

    load_tile(0, 0);
    int buf = 0;
    for (int kk = 0; kk < K; kk += BK) {
        const bool has_next = (kk + BK) < K;
        if (has_next) {
            load_tile(buf ^ 1, kk + BK);
            cp_wait1();
        } else {
            cp_wait0();
        }
        __syncthreads();

#pragma unroll
        for (int ks = 0; ks < BK; ks += 8) {
            wmma::fragment<wmma::matrix_a, 16, 16, 8, wmma::precision::tf32, wmma::row_major> af[2];
            wmma::fragment<wmma::matrix_b, 16, 16, 8, wmma::precision::tf32, wmma::col_major> bf[4];
#pragma unroll
            for (int i = 0; i < 2; i++) {
                wmma::load_matrix_sync(af[i], &As[(buf * BM + wm + i * 16) * LD + ks], LD);
#pragma unroll
                for (int e = 0; e < af[i].num_elements; e++)
                    af[i].x[e] = wmma::__float_to_tf32(af[i].x[e]);
            }
#pragma unroll
            for (int j = 0; j < 4; j++) {
                wmma::load_matrix_sync(bf[j], &Bs[(buf * BN + wn + j * 16) * LD + ks], LD);
#pragma unroll
                for (int e = 0; e < bf[j].num_elements; e++)
                    bf[j].x[e] = wmma::__float_to_tf32(bf[j].x[e]);
            }
#pragma unroll
            for (int i = 0; i < 2; i++)
#pragma unroll
                for (int j = 0; j < 4; j++)
                    wmma::mma_sync(acc[i][j], af[i], bf[j], acc[i][j]);
        }
        __syncthreads();
        buf ^= 1;
    }

#pragma unroll
    for (int i = 0; i < 2; i++)
#pragma unroll
        for (int j = 0; j < 4; j++) {
#pragma unroll
            for (int e = 0; e < acc[i][j].num_elements; e++) acc[i][j].x[e] *= alpha;
            wmma::store_matrix_sync(&C[(long)(tm + wm + i * 16) * N + tn + wn + j * 16],
                                    acc[i][j], N, wmma::mem_row_major);
        }
}

// ===========================================================================
// Plain TF32:  C = A(M,K) * B(K,N)   (row-major). Same pipeline; B tile 32x128.
// ===========================================================================
__global__ void __launch_bounds__(256, 2) gemm_ab_plain(
    const float* __restrict__ Ab, const float* __restrict__ Bb,
    float* __restrict__ Cb, int N, int K,
    long sA, long sB, long sC)
{
    constexpr int BM = 128, BN = 128, BK = 32, LDA = BK + 4, LDB = BN + 4;
    extern __shared__ float sm[];
    float* As = sm;                    // [2][BM][LDA]
    float* Bs = sm + 2 * BM * LDA;     // [2][BK][LDB]

    const float* A = Ab + (long)blockIdx.z * sA;
    const float* B = Bb + (long)blockIdx.z * sB;
    float*       C = Cb + (long)blockIdx.z * sC;

    const int tm   = blockIdx.y * BM;
    const int tn   = blockIdx.x * BN;
    const int tid  = threadIdx.x;
    const int warp = tid >> 5;
    const int wm   = (warp >> 1) * 32;
    const int wn   = (warp & 1) * 64;

    wmma::fragment<wmma::accumulator, 16, 16, 8, float> acc[2][4];
#pragma unroll
    for (int i = 0; i < 2; i++)
#pragma unroll
        for (int j = 0; j < 4; j++) wmma::fill_fragment(acc[i][j], 0.0f);

    const int ra0 = tid >> 3;          // A: 0..31 (x4 -> 128 rows), col (tid&7)*4
    const int ca0 = (tid & 7) << 2;
    const int rb0 = tid >> 5;          // B: 0..7 (x4 -> 32 rows), col (tid&31)*4
    const int cb0 = (tid & 31) << 2;

    auto load_tile = [&](int buf, int kk) {
#pragma unroll
        for (int i = 0; i < 4; i++) {
            int r = ra0 + i * 32;
            cp_async16(&As[(buf * BM + r) * LDA + ca0], &A[(long)(tm + r) * K + kk + ca0]);
        }
#pragma unroll
        for (int i = 0; i < 4; i++) {
            int r = rb0 + i * 8;
            cp_async16(&Bs[(buf * BK + r) * LDB + cb0], &B[(long)(kk + r) * N + tn + cb0]);
        }
        cp_commit();
    };

    load_tile(0, 0);
    int buf = 0;
    for (int kk = 0; kk < K; kk += BK) {
        const bool has_next = (kk + BK) < K;
        if (has_next) {
            load_tile(buf ^ 1, kk + BK);
            cp_wait1();
        } else {
            cp_wait0();
        }
        __syncthreads();

#pragma unroll
        for (int ks = 0; ks < BK; ks += 8) {
            wmma::fragment<wmma::matrix_a, 16, 16, 8, wmma::precision::tf32, wmma::row_major> af[2];
            wmma::fragment<wmma::matrix_b, 16, 16, 8, wmma::precision::tf32, wmma::row_major> bf[4];
#pragma unroll
            for (int i = 0; i < 2; i++) {
                wmma::load_matrix_sync(af[i], &As[(buf * BM + wm + i * 16) * LDA + ks], LDA);
#pragma unroll
                for (int e = 0; e < af[i].num_elements; e++)
                    af[i].x[e] = wmma::__float_to_tf32(af[i].x[e]);
            }
#pragma unroll
            for (int j = 0; j < 4; j++) {
                wmma::load_matrix_sync(bf[j], &Bs[(buf * BK + ks) * LDB + wn + j * 16], LDB);
#pragma unroll
                for (int e = 0; e < bf[j].num_elements; e++)
                    bf[j].x[e] = wmma::__float_to_tf32(bf[j].x[e]);
            }
#pragma unroll
            for (int i = 0; i < 2; i++)
#pragma unroll
                for (int j = 0; j < 4; j++)
                    wmma::mma_sync(acc[i][j], af[i], bf[j], acc[i][j]);
        }
        __syncthreads();
        buf ^= 1;
    }

#pragma unroll
    for (int i = 0; i < 2; i++)
#pragma unroll
        for (int j = 0; j < 4; j++)
            wmma::store_matrix_sync(&C[(long)(tm + wm + i * 16) * N + tn + wn + j * 16],
                                    acc[i][j], N, wmma::mem_row_major);
}

// ===========================================================================
// Precise (3xTF32):  C = A(M,K) * B(N,K)^T.  cp.async double buffering of raw
// fp32 tiles; hi/lo split at fragment load (round-1 numerics).
// ===========================================================================
__global__ void __launch_bounds__(256, 2) gemm_abT_precise(
    const float* __restrict__ A, const float* __restrict__ B,
    float* __restrict__ C, int N, int K)
{
    constexpr int BM = 128, BN = 128, BK = 32, LD = BK + 4;
    extern __shared__ float sm[];
    float* As = sm;                    // [2][BM][LD]
    float* Bs = sm + 2 * BM * LD;      // [2][BN][LD]

    const int tm   = blockIdx.y * BM;
    const int tn   = blockIdx.x * BN;
    const int tid  = threadIdx.x;
    const int warp = tid >> 5;
    const int wm   = (warp >> 1) * 32;
    const int wn   = (warp & 1) * 64;

    wmma::fragment<wmma::accumulator, 16, 16, 8, float> acc[2][4];
#pragma unroll
    for (int i = 0; i < 2; i++)
#pragma unroll
        for (int j = 0; j < 4; j++) wmma::fill_fragment(acc[i][j], 0.0f);

    const int r0 = tid >> 3;
    const int c0 = (tid & 7) << 2;

    auto load_tile = [&](int buf, int kk) {
#pragma unroll
        for (int i = 0; i < 4; i++) {
            int r = r0 + i * 32;
            cp_async16(&As[(buf * BM + r) * LD + c0], &A[(long)(tm + r) * K + kk + c0]);
            cp_async16(&Bs[(buf * BN + r) * LD + c0], &B[(long)(tn + r) * K + kk + c0]);
        }
        cp_commit();
    };

    load_tile(0, 0);
    int buf = 0;
    for (int kk = 0; kk < K; kk += BK) {
        const bool has_next = (kk + BK) < K;
        if (has_next) {
            load_tile(buf ^ 1, kk + BK);
            cp_wait1();
        } else {
            cp_wait0();
        }
        __syncthreads();

#pragma unroll
        for (int ks = 0; ks < BK; ks += 8) {
            wmma::fragment<wmma::matrix_a, 16, 16, 8, wmma::precision::tf32, wmma::row_major> ah[2], al[2];
            wmma::fragment<wmma::matrix_b, 16, 16, 8, wmma::precision::tf32, wmma::col_major> bh[4], bl[4];
#pragma unroll
            for (int i = 0; i < 2; i++) {
                wmma::load_matrix_sync(ah[i], &As[(buf * BM + wm + i * 16) * LD + ks], LD);
#pragma unroll
                for (int e = 0; e < ah[i].num_elements; e++) {
                    float x = ah[i].x[e];
                    float h = wmma::__float_to_tf32(x);
                    ah[i].x[e] = h;
                    al[i].x[e] = wmma::__float_to_tf32(x - h);
                }
            }
#pragma unroll
            for (int j = 0; j < 4; j++) {
                wmma::load_matrix_sync(bh[j], &Bs[(buf * BN + wn + j * 16) * LD + ks], LD);
#pragma unroll
                for (int e = 0; e < bh[j].num_elements; e++) {
                    float x = bh[j].x[e];
                    float h = wmma::__float_to_tf32(x);
                    bh[j].x[e] = h;
                    bl[j].x[e] = wmma::__float_to_tf32(x - h);
                }
            }
#pragma unroll
            for (int i = 0; i < 2; i++)
#pragma unroll
                for (int j = 0; j < 4; j++) {
                    wmma::mma_sync(acc[i][j], ah[i], bl[j], acc[i][j]);
                    wmma::mma_sync(acc[i][j], al[i], bh[j], acc[i][j]);
                    wmma::mma_sync(acc[i][j], ah[i], bh[j], acc[i][j]);
                }
        }
        __syncthreads();
        buf ^= 1;
    }

#pragma unroll
    for (int i = 0; i < 2; i++)
#pragma unroll
        for (int j = 0; j < 4; j++)
            wmma::store_matrix_sync(&C[(long)(tm + wm + i * 16) * N + tn + wn + j * 16],
                                    acc[i][j], N, wmma::mem_row_major);
}

// ---------------------------------------------------------------------------
// In-place row softmax over 4096-wide rows. One block (256 thr) per row.
// ---------------------------------------------------------------------------
__global__ void __launch_bounds__(256) softmax_kernel(float* __restrict__ Sg)
{
    float* row = Sg + (size_t)blockIdx.x * SQ;
    const int tid = threadIdx.x;
    __shared__ float red[8];

    float vals[16];
    float m = -3.4e38f;
#pragma unroll
    for (int i = 0; i < 16; i++) {
        vals[i] = row[tid + i * 256];
        m = fmaxf(m, vals[i]);
    }
#pragma unroll
    for (int o = 16; o; o >>= 1) m = fmaxf(m, __shfl_xor_sync(0xffffffffu, m, o));
    if ((tid & 31) == 0) red[tid >> 5] = m;
    __syncthreads();
    {
        float t = red[tid & 7];
#pragma unroll
        for (int o = 4; o; o >>= 1) t = fmaxf(t, __shfl_xor_sync(0xffffffffu, t, o));
        m = t;
    }

    float sum = 0.0f;
#pragma unroll
    for (int i = 0; i < 16; i++) {
        vals[i] = __expf(vals[i] - m);
        sum += vals[i];
    }
#pragma unroll
    for (int o = 16; o; o >>= 1) sum += __shfl_xor_sync(0xffffffffu, sum, o);
    __syncthreads();
    if ((tid & 31) == 0) red[tid >> 5] = sum;
    __syncthreads();
    {
        float t = red[tid & 7];
#pragma unroll
        for (int o = 4; o; o >>= 1) t += __shfl_xor_sync(0xffffffffu, t, o);
        sum = t;
    }

    float inv = 1.0f / sum;
#pragma unroll
    for (int i = 0; i < 16; i++) row[tid + i * 256] = vals[i] * inv;
}

// ---------------------------------------------------------------------------
extern "C" void kernel_launch(void* const* d_in, const int* in_sizes, int n_in,
                              void* d_out, int out_size)
{
    const float* x  = (const float*)d_in[0];   // (4, 4096, 1024)
    const float* Wq = (const float*)d_in[1];   // (1024, 1024)
    const float* Wk = (const float*)d_in[2];
    const float* Wv = (const float*)d_in[3];
    float* out = (float*)d_out;                // (4, 4096, 1024) fp32

    float *q, *k, *v, *s;
    cudaGetSymbolAddress((void**)&q, g_q);
    cudaGetSymbolAddress((void**)&k, g_k);
    cudaGetSymbolAddress((void**)&v, g_v);
    cudaGetSymbolAddress((void**)&s, g_s);

    constexpr int LD  = 32 + 4;
    const int smem_abT     = 2 * (128 * LD + 128 * LD) * 4;           // 73728
    const int smem_ab      = (2 * 128 * LD + 2 * 32 * (128 + 4)) * 4; // 70656
    const int smem_precise = 2 * (128 * LD + 128 * LD) * 4;           // 73728

    cudaFuncSetAttribute(gemm_abT_plain,   cudaFuncAttributeMaxDynamicSharedMemorySize, smem_abT);
    cudaFuncSetAttribute(gemm_ab_plain,    cudaFuncAttributeMaxDynamicSharedMemorySize, smem_ab);
    cudaFuncSetAttribute(gemm_abT_precise, cudaFuncAttributeMaxDynamicSharedMemorySize, smem_precise);

    const dim3 blk(256);

    // Phase 1: QKV projections (3xTF32). M = 16384, N = K = 1024.
    {
        dim3 grid(DM / 128, (NB * SQ) / 128, 1);
        gemm_abT_precise<<<grid, blk, smem_precise>>>(x, Wq, q, DM, DM);
        gemm_abT_precise<<<grid, blk, smem_precise>>>(x, Wk, k, DM, DM);
        gemm_abT_precise<<<grid, blk, smem_precise>>>(x, Wv, v, DM, DM);
    }

    // Phase 2: scores = (Q K^T) / 32, batched.
    {
        dim3 grid(SQ / 128, SQ / 128, NB);
        gemm_abT_plain<<<grid, blk, smem_abT>>>(q, k, s, SQ, DM,
                                                (long)SQ * DM, (long)SQ * DM,
                                                (long)SQ * SQ, 1.0f / 32.0f);
    }

    // Phase 3: row softmax (in place).
    softmax_kernel<<<NB * SQ, 256>>>(s);

    // Phase 4: out = P V, batched.
    {
        dim3 grid(DM / 128, SQ / 128, NB);
        gemm_ab_plain<<<grid, blk, smem_ab>>>(s, v, out, DM, SQ,
                                              (long)SQ * SQ, (long)SQ * DM,
                                              (long)SQ * DM);
    }
}

// round 8
// speedup vs baseline: 1.8096x; 1.4863x over previous
#include <cuda_runtime.h>
#include <cstdint>
#include <mma.h>
#include <math.h>
#include <cuda_bf16.h>

using namespace nvcuda;

#define DM   1024
#define NB   4
#define SQ   4096

// Scratch (device globals: the sanctioned alloc-free workaround)
__device__ float g_q[(size_t)NB * SQ * DM];
__device__ float g_k[(size_t)NB * SQ * DM];
__device__ float g_v[(size_t)NB * SQ * DM];
__device__ float g_s[(size_t)NB * SQ * SQ];
__device__ __nv_bfloat16 g_xh[(size_t)NB * SQ * DM];
__device__ __nv_bfloat16 g_xl[(size_t)NB * SQ * DM];
__device__ __nv_bfloat16 g_wh[3][(size_t)DM * DM];
__device__ __nv_bfloat16 g_wl[3][(size_t)DM * DM];

__device__ __forceinline__ void cp_async16(void* dst_smem, const void* src_gmem)
{
    uint32_t d = (uint32_t)__cvta_generic_to_shared(dst_smem);
    asm volatile("cp.async.cg.shared.global [%0], [%1], 16;\n" :: "r"(d), "l"(src_gmem));
}
__device__ __forceinline__ void cp_commit() { asm volatile("cp.async.commit_group;\n" ::); }
__device__ __forceinline__ void cp_wait0()  { asm volatile("cp.async.wait_group 0;\n" ::); }
__device__ __forceinline__ void cp_wait1()  { asm volatile("cp.async.wait_group 1;\n" ::); }

// ===========================================================================
// Elementwise split: fp32 -> bf16 hi + bf16 lo.  n must be a multiple of 4.
// ===========================================================================
__global__ void __launch_bounds__(256) split_bf16(
    const float* __restrict__ in, __nv_bfloat16* __restrict__ h,
    __nv_bfloat16* __restrict__ l, int n)
{
    int idx = (blockIdx.x * 256 + threadIdx.x) * 4;
    if (idx >= n) return;
    float4 v = *(const float4*)&in[idx];
    __nv_bfloat16 h0 = __float2bfloat16_rn(v.x);
    __nv_bfloat16 h1 = __float2bfloat16_rn(v.y);
    __nv_bfloat16 h2 = __float2bfloat16_rn(v.z);
    __nv_bfloat16 h3 = __float2bfloat16_rn(v.w);
    __nv_bfloat16 l0 = __float2bfloat16_rn(v.x - __bfloat162float(h0));
    __nv_bfloat16 l1 = __float2bfloat16_rn(v.y - __bfloat162float(h1));
    __nv_bfloat16 l2 = __float2bfloat16_rn(v.z - __bfloat162float(h2));
    __nv_bfloat16 l3 = __float2bfloat16_rn(v.w - __bfloat162float(h3));
    ushort4 hv = { __bfloat16_as_ushort(h0), __bfloat16_as_ushort(h1),
                   __bfloat16_as_ushort(h2), __bfloat16_as_ushort(h3) };
    ushort4 lv = { __bfloat16_as_ushort(l0), __bfloat16_as_ushort(l1),
                   __bfloat16_as_ushort(l2), __bfloat16_as_ushort(l3) };
    *(ushort4*)&h[idx] = hv;
    *(ushort4*)&l[idx] = lv;
}

// ===========================================================================
// QKV: C(M,N) = (Ah+Al)(M,K) x (Bh+Bl)(N,K)^T, bf16 3-term, fp32 accum.
// Epilogue rounds C to the tf32 grid so downstream GEMMs need no conversion.
// 128x128x32 tile, 256 threads (8 warps 4x2), warp tile 32x64, cp.async DB.
// ===========================================================================
__global__ void __launch_bounds__(256, 2) gemm_qkv_bf16(
    const __nv_bfloat16* __restrict__ Ah, const __nv_bfloat16* __restrict__ Al,
    const __nv_bfloat16* __restrict__ Bh, const __nv_bfloat16* __restrict__ Bl,
    float* __restrict__ C, int N, int K)
{
    constexpr int BM = 128, BN = 128, BK = 32, LD = BK + 16;  // bf16 elems
    extern __shared__ __align__(16) char smraw[];
    __nv_bfloat16* sAh = (__nv_bfloat16*)smraw;            // [2][BM][LD]
    __nv_bfloat16* sAl = sAh + 2 * BM * LD;
    __nv_bfloat16* sBh = sAl + 2 * BM * LD;                // [2][BN][LD]
    __nv_bfloat16* sBl = sBh + 2 * BN * LD;

    const int tm   = blockIdx.y * BM;
    const int tn   = blockIdx.x * BN;
    const int tid  = threadIdx.x;
    const int warp = tid >> 5;
    const int wm   = (warp >> 1) * 32;
    const int wn   = (warp & 1) * 64;

    wmma::fragment<wmma::accumulator, 16, 16, 16, float> acc[2][4];
#pragma unroll
    for (int i = 0; i < 2; i++)
#pragma unroll
        for (int j = 0; j < 4; j++) wmma::fill_fragment(acc[i][j], 0.0f);

    // Loader map: row = tid>>1 (0..127), 16B chunks cc, cc+1 (cc = (tid&1)*2).
    const int lr = tid >> 1;
    const int lc = (tid & 1) * 16;     // bf16 element offset (16 elems = 32B = 2 chunks)

    auto load_tile = [&](int buf, int kk) {
        long ga = (long)(tm + lr) * K + kk + lc;
        long gb = (long)(tn + lr) * K + kk + lc;
        int  sa = (buf * BM + lr) * LD + lc;
        int  sb = (buf * BN + lr) * LD + lc;
        cp_async16(&sAh[sa],     &Ah[ga]);
        cp_async16(&sAh[sa + 8], &Ah[ga + 8]);
        cp_async16(&sAl[sa],     &Al[ga]);
        cp_async16(&sAl[sa + 8], &Al[ga + 8]);
        cp_async16(&sBh[sb],     &Bh[gb]);
        cp_async16(&sBh[sb + 8], &Bh[gb + 8]);
        cp_async16(&sBl[sb],     &Bl[gb]);
        cp_async16(&sBl[sb + 8], &Bl[gb + 8]);
        cp_commit();
    };

    load_tile(0, 0);
    int buf = 0;
    for (int kk = 0; kk < K; kk += BK) {
        const bool has_next = (kk + BK) < K;
        if (has_next) {
            load_tile(buf ^ 1, kk + BK);
            cp_wait1();
        } else {
            cp_wait0();
        }
        __syncthreads();

#pragma unroll
        for (int ks = 0; ks < BK; ks += 16) {
            wmma::fragment<wmma::matrix_a, 16, 16, 16, __nv_bfloat16, wmma::row_major> ah[2], al[2];
            wmma::fragment<wmma::matrix_b, 16, 16, 16, __nv_bfloat16, wmma::col_major> bh[4], bl[4];
#pragma unroll
            for (int i = 0; i < 2; i++) {
                wmma::load_matrix_sync(ah[i], &sAh[(buf * BM + wm + i * 16) * LD + ks], LD);
                wmma::load_matrix_sync(al[i], &sAl[(buf * BM + wm + i * 16) * LD + ks], LD);
            }
#pragma unroll
            for (int j = 0; j < 4; j++) {
                wmma::load_matrix_sync(bh[j], &sBh[(buf * BN + wn + j * 16) * LD + ks], LD);
                wmma::load_matrix_sync(bl[j], &sBl[(buf * BN + wn + j * 16) * LD + ks], LD);
            }
#pragma unroll
            for (int i = 0; i < 2; i++)
#pragma unroll
                for (int j = 0; j < 4; j++) {
                    wmma::mma_sync(acc[i][j], ah[i], bl[j], acc[i][j]);
                    wmma::mma_sync(acc[i][j], al[i], bh[j], acc[i][j]);
                    wmma::mma_sync(acc[i][j], ah[i], bh[j], acc[i][j]);
                }
        }
        __syncthreads();
        buf ^= 1;
    }

#pragma unroll
    for (int i = 0; i < 2; i++)
#pragma unroll
        for (int j = 0; j < 4; j++) {
#pragma unroll
            for (int e = 0; e < acc[i][j].num_elements; e++)
                acc[i][j].x[e] = wmma::__float_to_tf32(acc[i][j].x[e]);
            wmma::store_matrix_sync(&C[(long)(tm + wm + i * 16) * N + tn + wn + j * 16],
                                    acc[i][j], N, wmma::mem_row_major);
        }
}

// ===========================================================================
// Plain TF32:  C = alpha * A(M,K) * B(N,K)^T.  Inputs are pre-rounded to the
// tf32 grid, so NO conversion in the mainloop. cp.async double buffering.
// ===========================================================================
__global__ void __launch_bounds__(256, 2) gemm_abT_plain(
    const float* __restrict__ Ab, const float* __restrict__ Bb,
    float* __restrict__ Cb, int N, int K,
    long sA, long sB, long sC, float alpha)
{
    constexpr int BM = 128, BN = 128, BK = 32, LD = BK + 4;
    extern __shared__ float sm[];
    float* As = sm;                    // [2][BM][LD]
    float* Bs = sm + 2 * BM * LD;      // [2][BN][LD]

    const float* A = Ab + (long)blockIdx.z * sA;
    const float* B = Bb + (long)blockIdx.z * sB;
    float*       C = Cb + (long)blockIdx.z * sC;

    const int tm   = blockIdx.y * BM;
    const int tn   = blockIdx.x * BN;
    const int tid  = threadIdx.x;
    const int warp = tid >> 5;
    const int wm   = (warp >> 1) * 32;
    const int wn   = (warp & 1) * 64;

    wmma::fragment<wmma::accumulator, 16, 16, 8, float> acc[2][4];
#pragma unroll
    for (int i = 0; i < 2; i++)
#pragma unroll
        for (int j = 0; j < 4; j++) wmma::fill_fragment(acc[i][j], 0.0f);

    const int r0 = tid >> 3;
    const int c0 = (tid & 7) << 2;

    auto load_tile = [&](int buf, int kk) {
#pragma unroll
        for (int i = 0; i < 4; i++) {
            int r = r0 + i * 32;
            cp_async16(&As[(buf * BM + r) * LD + c0], &A[(long)(tm + r) * K + kk + c0]);
            cp_async16(&Bs[(buf * BN + r) * LD + c0], &B[(long)(tn + r) * K + kk + c0]);
        }
        cp_commit();
    };

    load_tile(0, 0);
    int buf = 0;
    for (int kk = 0; kk < K; kk += BK) {
        const bool has_next = (kk + BK) < K;
        if (has_next) {
            load_tile(buf ^ 1, kk + BK);
            cp_wait1();
        } else {
            cp_wait0();
        }
        __syncthreads();

#pragma unroll
        for (int ks = 0; ks < BK; ks += 8) {
            wmma::fragment<wmma::matrix_a, 16, 16, 8, wmma::precision::tf32, wmma::row_major> af[2];
            wmma::fragment<wmma::matrix_b, 16, 16, 8, wmma::precision::tf32, wmma::col_major> bf[4];
#pragma unroll
            for (int i = 0; i < 2; i++)
                wmma::load_matrix_sync(af[i], &As[(buf * BM + wm + i * 16) * LD + ks], LD);
#pragma unroll
            for (int j = 0; j < 4; j++)
                wmma::load_matrix_sync(bf[j], &Bs[(buf * BN + wn + j * 16) * LD + ks], LD);
#pragma unroll
            for (int i = 0; i < 2; i++)
#pragma unroll
                for (int j = 0; j < 4; j++)
                    wmma::mma_sync(acc[i][j], af[i], bf[j], acc[i][j]);
        }
        __syncthreads();
        buf ^= 1;
    }

#pragma unroll
    for (int i = 0; i < 2; i++)
#pragma unroll
        for (int j = 0; j < 4; j++) {
#pragma unroll
            for (int e = 0; e < acc[i][j].num_elements; e++) acc[i][j].x[e] *= alpha;
            wmma::store_matrix_sync(&C[(long)(tm + wm + i * 16) * N + tn + wn + j * 16],
                                    acc[i][j], N, wmma::mem_row_major);
        }
}

// ===========================================================================
// Plain TF32:  C = A(M,K) * B(K,N).  Pre-rounded inputs, no mainloop cvt.
// ===========================================================================
__global__ void __launch_bounds__(256, 2) gemm_ab_plain(
    const float* __restrict__ Ab, const float* __restrict__ Bb,
    float* __restrict__ Cb, int N, int K,
    long sA, long sB, long sC)
{
    constexpr int BM = 128, BN = 128, BK = 32, LDA = BK + 4, LDB = BN + 4;
    extern __shared__ float sm[];
    float* As = sm;                    // [2][BM][LDA]
    float* Bs = sm + 2 * BM * LDA;     // [2][BK][LDB]

    const float* A = Ab + (long)blockIdx.z * sA;
    const float* B = Bb + (long)blockIdx.z * sB;
    float*       C = Cb + (long)blockIdx.z * sC;

    const int tm   = blockIdx.y * BM;
    const int tn   = blockIdx.x * BN;
    const int tid  = threadIdx.x;
    const int warp = tid >> 5;
    const int wm   = (warp >> 1) * 32;
    const int wn   = (warp & 1) * 64;

    wmma::fragment<wmma::accumulator, 16, 16, 8, float> acc[2][4];
#pragma unroll
    for (int i = 0; i < 2; i++)
#pragma unroll
        for (int j = 0; j < 4; j++) wmma::fill_fragment(acc[i][j], 0.0f);

    const int ra0 = tid >> 3;
    const int ca0 = (tid & 7) << 2;
    const int rb0 = tid >> 5;
    const int cb0 = (tid & 31) << 2;

    auto load_tile = [&](int buf, int kk) {
#pragma unroll
        for (int i = 0; i < 4; i++) {
            int r = ra0 + i * 32;
            cp_async16(&As[(buf * BM + r) * LDA + ca0], &A[(long)(tm + r) * K + kk + ca0]);
        }
#pragma unroll
        for (int i = 0; i < 4; i++) {
            int r = rb0 + i * 8;
            cp_async16(&Bs[(buf * BK + r) * LDB + cb0], &B[(long)(kk + r) * N + tn + cb0]);
        }
        cp_commit();
    };

    load_tile(0, 0);
    int buf = 0;
    for (int kk = 0; kk < K; kk += BK) {
        const bool has_next = (kk + BK) < K;
        if (has_next) {
            load_tile(buf ^ 1, kk + BK);
            cp_wait1();
        } else {
            cp_wait0();
        }
        __syncthreads();

#pragma unroll
        for (int ks = 0; ks < BK; ks += 8) {
            wmma::fragment<wmma::matrix_a, 16, 16, 8, wmma::precision::tf32, wmma::row_major> af[2];
            wmma::fragment<wmma::matrix_b, 16, 16, 8, wmma::precision::tf32, wmma::row_major> bf[4];
#pragma unroll
            for (int i = 0; i < 2; i++)
                wmma::load_matrix_sync(af[i], &As[(buf * BM + wm + i * 16) * LDA + ks], LDA);
#pragma unroll
            for (int j = 0; j < 4; j++)
                wmma::load_matrix_sync(bf[j], &Bs[(buf * BK + ks) * LDB + wn + j * 16], LDB);
#pragma unroll
            for (int i = 0; i < 2; i++)
#pragma unroll
                for (int j = 0; j < 4; j++)
                    wmma::mma_sync(acc[i][j], af[i], bf[j], acc[i][j]);
        }
        __syncthreads();
        buf ^= 1;
    }

#pragma unroll
    for (int i = 0; i < 2; i++)
#pragma unroll
        for (int j = 0; j < 4; j++)
            wmma::store_matrix_sync(&C[(long)(tm + wm + i * 16) * N + tn + wn + j * 16],
                                    acc[i][j], N, wmma::mem_row_major);
}

// ---------------------------------------------------------------------------
// In-place row softmax over 4096-wide rows; output rounded to the tf32 grid
// so the PV GEMM needs no conversion.
// ---------------------------------------------------------------------------
__global__ void __launch_bounds__(256) softmax_kernel(float* __restrict__ Sg)
{
    float* row = Sg + (size_t)blockIdx.x * SQ;
    const int tid = threadIdx.x;
    __shared__ float red[8];

    float vals[16];
    float m = -3.4e38f;
#pragma unroll
    for (int i = 0; i < 16; i++) {
        vals[i] = row[tid + i * 256];
        m = fmaxf(m, vals[i]);
    }
#pragma unroll
    for (int o = 16; o; o >>= 1) m = fmaxf(m, __shfl_xor_sync(0xffffffffu, m, o));
    if ((tid & 31) == 0) red[tid >> 5] = m;
    __syncthreads();
    {
        float t = red[tid & 7];
#pragma unroll
        for (int o = 4; o; o >>= 1) t = fmaxf(t, __shfl_xor_sync(0xffffffffu, t, o));
        m = t;
    }

    float sum = 0.0f;
#pragma unroll
    for (int i = 0; i < 16; i++) {
        vals[i] = __expf(vals[i] - m);
        sum += vals[i];
    }
#pragma unroll
    for (int o = 16; o; o >>= 1) sum += __shfl_xor_sync(0xffffffffu, sum, o);
    __syncthreads();
    if ((tid & 31) == 0) red[tid >> 5] = sum;
    __syncthreads();
    {
        float t = red[tid & 7];
#pragma unroll
        for (int o = 4; o; o >>= 1) t += __shfl_xor_sync(0xffffffffu, t, o);
        sum = t;
    }

    float inv = 1.0f / sum;
#pragma unroll
    for (int i = 0; i < 16; i++)
        row[tid + i * 256] = wmma::__float_to_tf32(vals[i] * inv);
}

// ---------------------------------------------------------------------------
extern "C" void kernel_launch(void* const* d_in, const int* in_sizes, int n_in,
                              void* d_out, int out_size)
{
    const float* x  = (const float*)d_in[0];   // (4, 4096, 1024)
    const float* Wq = (const float*)d_in[1];   // (1024, 1024)
    const float* Wk = (const float*)d_in[2];
    const float* Wv = (const float*)d_in[3];
    float* out = (float*)d_out;                // (4, 4096, 1024) fp32

    float *q, *k, *v, *s;
    __nv_bfloat16 *xh, *xl, *wh, *wl;
    cudaGetSymbolAddress((void**)&q,  g_q);
    cudaGetSymbolAddress((void**)&k,  g_k);
    cudaGetSymbolAddress((void**)&v,  g_v);
    cudaGetSymbolAddress((void**)&s,  g_s);
    cudaGetSymbolAddress((void**)&xh, g_xh);
    cudaGetSymbolAddress((void**)&xl, g_xl);
    cudaGetSymbolAddress((void**)&wh, g_wh);
    cudaGetSymbolAddress((void**)&wl, g_wl);

    const int smem_abT  = 2 * (128 * 36 + 128 * 36) * 4;            // 73728
    const int smem_ab   = (2 * 128 * 36 + 2 * 32 * 132) * 4;        // 70656
    const int smem_qkv  = 2 * 4 * 128 * 48 * 2;                     // 98304

    cudaFuncSetAttribute(gemm_abT_plain, cudaFuncAttributeMaxDynamicSharedMemorySize, smem_abT);
    cudaFuncSetAttribute(gemm_ab_plain,  cudaFuncAttributeMaxDynamicSharedMemorySize, smem_ab);
    cudaFuncSetAttribute(gemm_qkv_bf16,  cudaFuncAttributeMaxDynamicSharedMemorySize, smem_qkv);

    const dim3 blk(256);
    const int nx = NB * SQ * DM;       // 16,777,216
    const int nw = DM * DM;            // 1,048,576

    // Phase 0: hi/lo bf16 splits.
    split_bf16<<<nx / 4 / 256, blk>>>(x,  xh, xl, nx);
    split_bf16<<<nw / 4 / 256, blk>>>(Wq, wh + 0L * nw, wl + 0L * nw, nw);
    split_bf16<<<nw / 4 / 256, blk>>>(Wk, wh + 1L * nw, wl + 1L * nw, nw);
    split_bf16<<<nw / 4 / 256, blk>>>(Wv, wh + 2L * nw, wl + 2L * nw, nw);

    // Phase 1: QKV projections (3-term bf16), outputs tf32-rounded.
    {
        dim3 grid(DM / 128, (NB * SQ) / 128, 1);
        gemm_qkv_bf16<<<grid, blk, smem_qkv>>>(xh, xl, wh + 0L * nw, wl + 0L * nw, q, DM, DM);
        gemm_qkv_bf16<<<grid, blk, smem_qkv>>>(xh, xl, wh + 1L * nw, wl + 1L * nw, k, DM, DM);
        gemm_qkv_bf16<<<grid, blk, smem_qkv>>>(xh, xl, wh + 2L * nw, wl + 2L * nw, v, DM, DM);
    }

    // Phase 2: scores = (Q K^T) / 32, batched.
    {
        dim3 grid(SQ / 128, SQ / 128, NB);
        gemm_abT_plain<<<grid, blk, smem_abT>>>(q, k, s, SQ, DM,
                                                (long)SQ * DM, (long)SQ * DM,
                                                (long)SQ * SQ, 1.0f / 32.0f);
    }

    // Phase 3: row softmax (in place), tf32-rounded output.
    softmax_kernel<<<NB * SQ, 256>>>(s);

    // Phase 4: out = P V, batched.
    {
        dim3 grid(DM / 128, SQ / 128, NB);
        gemm_ab_plain<<<grid, blk, smem_ab>>>(s, v, out, DM, SQ,
                                              (long)SQ * SQ, (long)SQ * DM,
                                              (long)SQ * DM);
    }
}

// round 10
// speedup vs baseline: 1.8915x; 1.0453x over previous
#include <cuda_runtime.h>
#include <cstdint>
#include <mma.h>
#include <math.h>
#include <cuda_bf16.h>
#include <cuda_fp16.h>

using namespace nvcuda;

#define DM   1024
#define NB   4
#define SQ   4096

// Scratch (device globals: the sanctioned alloc-free workaround)
__device__ float g_q[(size_t)NB * SQ * DM];
__device__ float g_k[(size_t)NB * SQ * DM];
__device__ float g_v[(size_t)NB * SQ * DM];
__device__ float g_s[(size_t)NB * SQ * SQ];
__device__ __nv_bfloat16 g_xh[(size_t)NB * SQ * DM];
__device__ __nv_bfloat16 g_xl[(size_t)NB * SQ * DM];
__device__ __nv_bfloat16 g_wh[3][(size_t)DM * DM];
__device__ __nv_bfloat16 g_wl[3][(size_t)DM * DM];

__device__ __forceinline__ void cp_async16(void* dst_smem, const void* src_gmem)
{
    uint32_t d = (uint32_t)__cvta_generic_to_shared(dst_smem);
    asm volatile("cp.async.cg.shared.global [%0], [%1], 16;\n" :: "r"(d), "l"(src_gmem));
}
__device__ __forceinline__ void cp_commit() { asm volatile("cp.async.commit_group;\n" ::); }
__device__ __forceinline__ void cp_wait0()  { asm volatile("cp.async.wait_group 0;\n" ::); }
__device__ __forceinline__ void cp_wait1()  { asm volatile("cp.async.wait_group 1;\n" ::); }

// ===========================================================================
// Elementwise split: fp32 -> bf16 hi + bf16 lo.
// ===========================================================================
__global__ void __launch_bounds__(256) split_bf16(
    const float* __restrict__ in, __nv_bfloat16* __restrict__ h,
    __nv_bfloat16* __restrict__ l, int n)
{
    int idx = (blockIdx.x * 256 + threadIdx.x) * 4;
    if (idx >= n) return;
    float4 v = *(const float4*)&in[idx];
    __nv_bfloat16 h0 = __float2bfloat16_rn(v.x);
    __nv_bfloat16 h1 = __float2bfloat16_rn(v.y);
    __nv_bfloat16 h2 = __float2bfloat16_rn(v.z);
    __nv_bfloat16 h3 = __float2bfloat16_rn(v.w);
    __nv_bfloat16 l0 = __float2bfloat16_rn(v.x - __bfloat162float(h0));
    __nv_bfloat16 l1 = __float2bfloat16_rn(v.y - __bfloat162float(h1));
    __nv_bfloat16 l2 = __float2bfloat16_rn(v.z - __bfloat162float(h2));
    __nv_bfloat16 l3 = __float2bfloat16_rn(v.w - __bfloat162float(h3));
    ushort4 hv = { __bfloat16_as_ushort(h0), __bfloat16_as_ushort(h1),
                   __bfloat16_as_ushort(h2), __bfloat16_as_ushort(h3) };
    ushort4 lv = { __bfloat16_as_ushort(l0), __bfloat16_as_ushort(l1),
                   __bfloat16_as_ushort(l2), __bfloat16_as_ushort(l3) };
    *(ushort4*)&h[idx] = hv;
    *(ushort4*)&l[idx] = lv;
}

// ===========================================================================
// QKV: C(M,N) = (Ah+Al)(M,K) x (Bh+Bl)(N,K)^T, bf16 3-term, fp32 accum.
// Epilogue rounds C to the tf32 grid. 2-stage cp.async (unchanged from R8).
// ===========================================================================
__global__ void __launch_bounds__(256, 2) gemm_qkv_bf16(
    const __nv_bfloat16* __restrict__ Ah, const __nv_bfloat16* __restrict__ Al,
    const __nv_bfloat16* __restrict__ Bh, const __nv_bfloat16* __restrict__ Bl,
    float* __restrict__ C, int N, int K)
{
    constexpr int BM = 128, BN = 128, BK = 32, LD = BK + 16;  // bf16 elems
    extern __shared__ __align__(16) char smraw[];
    __nv_bfloat16* sAh = (__nv_bfloat16*)smraw;            // [2][BM][LD]
    __nv_bfloat16* sAl = sAh + 2 * BM * LD;
    __nv_bfloat16* sBh = sAl + 2 * BM * LD;                // [2][BN][LD]
    __nv_bfloat16* sBl = sBh + 2 * BN * LD;

    const int tm   = blockIdx.y * BM;
    const int tn   = blockIdx.x * BN;
    const int tid  = threadIdx.x;
    const int warp = tid >> 5;
    const int wm   = (warp >> 1) * 32;
    const int wn   = (warp & 1) * 64;

    wmma::fragment<wmma::accumulator, 16, 16, 16, float> acc[2][4];
#pragma unroll
    for (int i = 0; i < 2; i++)
#pragma unroll
        for (int j = 0; j < 4; j++) wmma::fill_fragment(acc[i][j], 0.0f);

    const int lr = tid >> 1;
    const int lc = (tid & 1) * 16;

    auto load_tile = [&](int buf, int kk) {
        long ga = (long)(tm + lr) * K + kk + lc;
        long gb = (long)(tn + lr) * K + kk + lc;
        int  sa = (buf * BM + lr) * LD + lc;
        int  sb = (buf * BN + lr) * LD + lc;
        cp_async16(&sAh[sa],     &Ah[ga]);
        cp_async16(&sAh[sa + 8], &Ah[ga + 8]);
        cp_async16(&sAl[sa],     &Al[ga]);
        cp_async16(&sAl[sa + 8], &Al[ga + 8]);
        cp_async16(&sBh[sb],     &Bh[gb]);
        cp_async16(&sBh[sb + 8], &Bh[gb + 8]);
        cp_async16(&sBl[sb],     &Bl[gb]);
        cp_async16(&sBl[sb + 8], &Bl[gb + 8]);
        cp_commit();
    };

    load_tile(0, 0);
    int buf = 0;
    for (int kk = 0; kk < K; kk += BK) {
        const bool has_next = (kk + BK) < K;
        if (has_next) {
            load_tile(buf ^ 1, kk + BK);
            cp_wait1();
        } else {
            cp_wait0();
        }
        __syncthreads();

#pragma unroll
        for (int ks = 0; ks < BK; ks += 16) {
            wmma::fragment<wmma::matrix_a, 16, 16, 16, __nv_bfloat16, wmma::row_major> ah[2], al[2];
            wmma::fragment<wmma::matrix_b, 16, 16, 16, __nv_bfloat16, wmma::col_major> bh[4], bl[4];
#pragma unroll
            for (int i = 0; i < 2; i++) {
                wmma::load_matrix_sync(ah[i], &sAh[(buf * BM + wm + i * 16) * LD + ks], LD);
                wmma::load_matrix_sync(al[i], &sAl[(buf * BM + wm + i * 16) * LD + ks], LD);
            }
#pragma unroll
            for (int j = 0; j < 4; j++) {
                wmma::load_matrix_sync(bh[j], &sBh[(buf * BN + wn + j * 16) * LD + ks], LD);
                wmma::load_matrix_sync(bl[j], &sBl[(buf * BN + wn + j * 16) * LD + ks], LD);
            }
#pragma unroll
            for (int i = 0; i < 2; i++)
#pragma unroll
                for (int j = 0; j < 4; j++) {
                    wmma::mma_sync(acc[i][j], ah[i], bl[j], acc[i][j]);
                    wmma::mma_sync(acc[i][j], al[i], bh[j], acc[i][j]);
                    wmma::mma_sync(acc[i][j], ah[i], bh[j], acc[i][j]);
                }
        }
        __syncthreads();
        buf ^= 1;
    }

#pragma unroll
    for (int i = 0; i < 2; i++)
#pragma unroll
        for (int j = 0; j < 4; j++) {
#pragma unroll
            for (int e = 0; e < acc[i][j].num_elements; e++)
                acc[i][j].x[e] = wmma::__float_to_tf32(acc[i][j].x[e]);
            wmma::store_matrix_sync(&C[(long)(tm + wm + i * 16) * N + tn + wn + j * 16],
                                    acc[i][j], N, wmma::mem_row_major);
        }
}

// ===========================================================================
// Plain TF32:  C = alpha * A(M,K) * B(N,K)^T.  Pre-rounded inputs.
// 3-stage cp.async pipeline, ONE __syncthreads per k-iter.
// ===========================================================================
__global__ void __launch_bounds__(256, 2) gemm_abT_plain(
    const float* __restrict__ Ab, const float* __restrict__ Bb,
    float* __restrict__ Cb, int N, int K,
    long sA, long sB, long sC, float alpha)
{
    constexpr int BM = 128, BN = 128, BK = 32, LD = BK + 4;
    extern __shared__ float sm[];
    float* As = sm;                    // [3][BM][LD]
    float* Bs = sm + 3 * BM * LD;      // [3][BN][LD]

    const float* A = Ab + (long)blockIdx.z * sA;
    const float* B = Bb + (long)blockIdx.z * sB;
    float*       C = Cb + (long)blockIdx.z * sC;

    const int tm   = blockIdx.y * BM;
    const int tn   = blockIdx.x * BN;
    const int tid  = threadIdx.x;
    const int warp = tid >> 5;
    const int wm   = (warp >> 1) * 32;
    const int wn   = (warp & 1) * 64;

    wmma::fragment<wmma::accumulator, 16, 16, 8, float> acc[2][4];
#pragma unroll
    for (int i = 0; i < 2; i++)
#pragma unroll
        for (int j = 0; j < 4; j++) wmma::fill_fragment(acc[i][j], 0.0f);

    const int r0 = tid >> 3;
    const int c0 = (tid & 7) << 2;

    auto load_tile = [&](int buf, int kk) {
#pragma unroll
        for (int i = 0; i < 4; i++) {
            int r = r0 + i * 32;
            cp_async16(&As[(buf * BM + r) * LD + c0], &A[(long)(tm + r) * K + kk + c0]);
            cp_async16(&Bs[(buf * BN + r) * LD + c0], &B[(long)(tn + r) * K + kk + c0]);
        }
        cp_commit();
    };

    const int NCH = K / BK;
    load_tile(0, 0);
    load_tile(1, BK);

    int buf = 0;
    for (int c = 0; c < NCH; c++) {
        if (c + 1 < NCH) cp_wait1(); else cp_wait0();
        __syncthreads();

#pragma unroll
        for (int ks = 0; ks < BK; ks += 8) {
            wmma::fragment<wmma::matrix_a, 16, 16, 8, wmma::precision::tf32, wmma::row_major> af[2];
            wmma::fragment<wmma::matrix_b, 16, 16, 8, wmma::precision::tf32, wmma::col_major> bf[4];
#pragma unroll
            for (int i = 0; i < 2; i++)
                wmma::load_matrix_sync(af[i], &As[(buf * BM + wm + i * 16) * LD + ks], LD);
#pragma unroll
            for (int j = 0; j < 4; j++)
                wmma::load_matrix_sync(bf[j], &Bs[(buf * BN + wn + j * 16) * LD + ks], LD);
#pragma unroll
            for (int i = 0; i < 2; i++)
#pragma unroll
                for (int j = 0; j < 4; j++)
                    wmma::mma_sync(acc[i][j], af[i], bf[j], acc[i][j]);
        }

        if (c + 2 < NCH) {
            int nb = buf + 2; if (nb >= 3) nb -= 3;
            load_tile(nb, (c + 2) * BK);
        }
        buf = (buf + 1 == 3) ? 0 : buf + 1;
    }

#pragma unroll
    for (int i = 0; i < 2; i++)
#pragma unroll
        for (int j = 0; j < 4; j++) {
#pragma unroll
            for (int e = 0; e < acc[i][j].num_elements; e++) acc[i][j].x[e] *= alpha;
            wmma::store_matrix_sync(&C[(long)(tm + wm + i * 16) * N + tn + wn + j * 16],
                                    acc[i][j], N, wmma::mem_row_major);
        }
}

// ===========================================================================
// Plain TF32:  C = A(M,K) * B(K,N).  Pre-rounded inputs, 3-stage pipeline.
// ===========================================================================
__global__ void __launch_bounds__(256, 2) gemm_ab_plain(
    const float* __restrict__ Ab, const float* __restrict__ Bb,
    float* __restrict__ Cb, int N, int K,
    long sA, long sB, long sC)
{
    constexpr int BM = 128, BN = 128, BK = 32, LDA = BK + 4, LDB = BN + 4;
    extern __shared__ float sm[];
    float* As = sm;                    // [3][BM][LDA]
    float* Bs = sm + 3 * BM * LDA;     // [3][BK][LDB]

    const float* A = Ab + (long)blockIdx.z * sA;
    const float* B = Bb + (long)blockIdx.z * sB;
    float*       C = Cb + (long)blockIdx.z * sC;

    const int tm   = blockIdx.y * BM;
    const int tn   = blockIdx.x * BN;
    const int tid  = threadIdx.x;
    const int warp = tid >> 5;
    const int wm   = (warp >> 1) * 32;
    const int wn   = (warp & 1) * 64;

    wmma::fragment<wmma::accumulator, 16, 16, 8, float> acc[2][4];
#pragma unroll
    for (int i = 0; i < 2; i++)
#pragma unroll
        for (int j = 0; j < 4; j++) wmma::fill_fragment(acc[i][j], 0.0f);

    const int ra0 = tid >> 3;
    const int ca0 = (tid & 7) << 2;
    const int rb0 = tid >> 5;
    const int cb0 = (tid & 31) << 2;

    auto load_tile = [&](int buf, int kk) {
#pragma unroll
        for (int i = 0; i < 4; i++) {
            int r = ra0 + i * 32;
            cp_async16(&As[(buf * BM + r) * LDA + ca0], &A[(long)(tm + r) * K + kk + ca0]);
        }
#pragma unroll
        for (int i = 0; i < 4; i++) {
            int r = rb0 + i * 8;
            cp_async16(&Bs[(buf * BK + r) * LDB + cb0], &B[(long)(kk + r) * N + tn + cb0]);
        }
        cp_commit();
    };

    const int NCH = K / BK;
    load_tile(0, 0);
    load_tile(1, BK);

    int buf = 0;
    for (int c = 0; c < NCH; c++) {
        if (c + 1 < NCH) cp_wait1(); else cp_wait0();
        __syncthreads();

#pragma unroll
        for (int ks = 0; ks < BK; ks += 8) {
            wmma::fragment<wmma::matrix_a, 16, 16, 8, wmma::precision::tf32, wmma::row_major> af[2];
            wmma::fragment<wmma::matrix_b, 16, 16, 8, wmma::precision::tf32, wmma::row_major> bf[4];
#pragma unroll
            for (int i = 0; i < 2; i++)
                wmma::load_matrix_sync(af[i], &As[(buf * BM + wm + i * 16) * LDA + ks], LDA);
#pragma unroll
            for (int j = 0; j < 4; j++)
                wmma::load_matrix_sync(bf[j], &Bs[(buf * BK + ks) * LDB + wn + j * 16], LDB);
#pragma unroll
            for (int i = 0; i < 2; i++)
#pragma unroll
                for (int j = 0; j < 4; j++)
                    wmma::mma_sync(acc[i][j], af[i], bf[j], acc[i][j]);
        }

        if (c + 2 < NCH) {
            int nb = buf + 2; if (nb >= 3) nb -= 3;
            load_tile(nb, (c + 2) * BK);
        }
        buf = (buf + 1 == 3) ? 0 : buf + 1;
    }

#pragma unroll
    for (int i = 0; i < 2; i++)
#pragma unroll
        for (int j = 0; j < 4; j++)
            wmma::store_matrix_sync(&C[(long)(tm + wm + i * 16) * N + tn + wn + j * 16],
                                    acc[i][j], N, wmma::mem_row_major);
}

// ---------------------------------------------------------------------------
// In-place row softmax over 4096-wide rows; exp computed on f16x2 (one MUFU
// op per two elements); output rounded to the tf32 grid.
// ---------------------------------------------------------------------------
__global__ void __launch_bounds__(256) softmax_kernel(float* __restrict__ Sg)
{
    float* row = Sg + (size_t)blockIdx.x * SQ;
    const int tid = threadIdx.x;
    __shared__ float red[8];

    float vals[16];
    float m = -3.4e38f;
#pragma unroll
    for (int i = 0; i < 16; i++) {
        vals[i] = row[tid + i * 256];
        m = fmaxf(m, vals[i]);
    }
#pragma unroll
    for (int o = 16; o; o >>= 1) m = fmaxf(m, __shfl_xor_sync(0xffffffffu, m, o));
    if ((tid & 31) == 0) red[tid >> 5] = m;
    __syncthreads();
    {
        float t = red[tid & 7];
#pragma unroll
        for (int o = 4; o; o >>= 1) t = fmaxf(t, __shfl_xor_sync(0xffffffffu, t, o));
        m = t;
    }

    float sum = 0.0f;
#pragma unroll
    for (int i = 0; i < 8; i++) {
        __half2 x = __floats2half2_rn(vals[2 * i] - m, vals[2 * i + 1] - m);
        float2 e = __half22float2(h2exp(x));
        vals[2 * i]     = e.x;
        vals[2 * i + 1] = e.y;
        sum += e.x + e.y;
    }
#pragma unroll
    for (int o = 16; o; o >>= 1) sum += __shfl_xor_sync(0xffffffffu, sum, o);
    __syncthreads();
    if ((tid & 31) == 0) red[tid >> 5] = sum;
    __syncthreads();
    {
        float t = red[tid & 7];
#pragma unroll
        for (int o = 4; o; o >>= 1) t += __shfl_xor_sync(0xffffffffu, t, o);
        sum = t;
    }

    float inv = 1.0f / sum;
#pragma unroll
    for (int i = 0; i < 16; i++)
        row[tid + i * 256] = wmma::__float_to_tf32(vals[i] * inv);
}

// ---------------------------------------------------------------------------
extern "C" void kernel_launch(void* const* d_in, const int* in_sizes, int n_in,
                              void* d_out, int out_size)
{
    const float* x  = (const float*)d_in[0];
    const float* Wq = (const float*)d_in[1];
    const float* Wk = (const float*)d_in[2];
    const float* Wv = (const float*)d_in[3];
    float* out = (float*)d_out;

    float *q, *k, *v, *s;
    __nv_bfloat16 *xh, *xl, *wh, *wl;
    cudaGetSymbolAddress((void**)&q,  g_q);
    cudaGetSymbolAddress((void**)&k,  g_k);
    cudaGetSymbolAddress((void**)&v,  g_v);
    cudaGetSymbolAddress((void**)&s,  g_s);
    cudaGetSymbolAddress((void**)&xh, g_xh);
    cudaGetSymbolAddress((void**)&xl, g_xl);
    cudaGetSymbolAddress((void**)&wh, g_wh);
    cudaGetSymbolAddress((void**)&wl, g_wl);

    const int smem_abT  = 3 * (128 * 36 + 128 * 36) * 4;            // 110592
    const int smem_ab   = 3 * (128 * 36 * 4 + 32 * 132 * 4);        // 105984
    const int smem_qkv  = 2 * 4 * 128 * 48 * 2;                     // 98304

    cudaFuncSetAttribute(gemm_abT_plain, cudaFuncAttributeMaxDynamicSharedMemorySize, smem_abT);
    cudaFuncSetAttribute(gemm_ab_plain,  cudaFuncAttributeMaxDynamicSharedMemorySize, smem_ab);
    cudaFuncSetAttribute(gemm_qkv_bf16,  cudaFuncAttributeMaxDynamicSharedMemorySize, smem_qkv);

    const dim3 blk(256);
    const int nx = NB * SQ * DM;
    const int nw = DM * DM;

    // Phase 0: hi/lo bf16 splits.
    split_bf16<<<nx / 4 / 256, blk>>>(x,  xh, xl, nx);
    split_bf16<<<nw / 4 / 256, blk>>>(Wq, wh + 0L * nw, wl + 0L * nw, nw);
    split_bf16<<<nw / 4 / 256, blk>>>(Wk, wh + 1L * nw, wl + 1L * nw, nw);
    split_bf16<<<nw / 4 / 256, blk>>>(Wv, wh + 2L * nw, wl + 2L * nw, nw);

    // Phase 1: QKV projections (3-term bf16), outputs tf32-rounded.
    {
        dim3 grid(DM / 128, (NB * SQ) / 128, 1);
        gemm_qkv_bf16<<<grid, blk, smem_qkv>>>(xh, xl, wh + 0L * nw, wl + 0L * nw, q, DM, DM);
        gemm_qkv_bf16<<<grid, blk, smem_qkv>>>(xh, xl, wh + 1L * nw, wl + 1L * nw, k, DM, DM);
        gemm_qkv_bf16<<<grid, blk, smem_qkv>>>(xh, xl, wh + 2L * nw, wl + 2L * nw, v, DM, DM);
    }

    // Phase 2: scores = (Q K^T) / 32, batched.
    {
        dim3 grid(SQ / 128, SQ / 128, NB);
        gemm_abT_plain<<<grid, blk, smem_abT>>>(q, k, s, SQ, DM,
                                                (long)SQ * DM, (long)SQ * DM,
                                                (long)SQ * SQ, 1.0f / 32.0f);
    }

    // Phase 3: row softmax (in place), f16x2 exp, tf32-rounded output.
    softmax_kernel<<<NB * SQ, 256>>>(s);

    // Phase 4: out = P V, batched.
    {
        dim3 grid(DM / 128, SQ / 128, NB);
        gemm_ab_plain<<<grid, blk, smem_ab>>>(s, v, out, DM, SQ,
                                              (long)SQ * SQ, (long)SQ * DM,
                                              (long)SQ * DM);
    }
}